// round 2
// baseline (speedup 1.0000x reference)
#include <cuda_runtime.h>
#include <math.h>

#define BB 8
#define NN 2048
#define FI 128
#define FO 64
#define LRALPHA 0.2f
#define TI 64
#define TJ 64
#define NT (NN / TJ)

// scratch (static device arrays: allocation-free)
__device__ float g_Wh[(size_t)BB * NN * FO];   // 4 MB
__device__ float g_s1[BB * NN];
__device__ float g_s2[BB * NN];

// ---------------------------------------------------------------------------
// Kernel 1: Wh = h @ W   (rows = B*N = 16384, 16 rows / block)
// ---------------------------------------------------------------------------
__global__ void __launch_bounds__(256) wh_kernel(const float* __restrict__ h,
                                                 const float* __restrict__ W) {
    __shared__ float sW[FI * FO];   // 32 KB
    __shared__ float sh[16 * FI];   // 8 KB
    const int tid  = threadIdx.x;
    const int row0 = blockIdx.x * 16;

    const float4* W4 = (const float4*)W;
    float4* sW4 = (float4*)sW;
    #pragma unroll 2
    for (int idx = tid; idx < FI * FO / 4; idx += 256) sW4[idx] = W4[idx];

    const float4* h4 = (const float4*)(h + (size_t)row0 * FI);
    float4* sh4 = (float4*)sh;
    #pragma unroll 2
    for (int idx = tid; idx < 16 * FI / 4; idx += 256) sh4[idx] = h4[idx];
    __syncthreads();

    const int f  = tid & 63;
    const int rg = tid >> 6;   // 0..3 -> rows rg, rg+4, rg+8, rg+12
    float a0 = 0.f, a1 = 0.f, a2 = 0.f, a3 = 0.f;
    #pragma unroll 8
    for (int k = 0; k < FI; ++k) {
        const float wv = sW[k * FO + f];
        a0 = fmaf(sh[(rg +  0) * FI + k], wv, a0);
        a1 = fmaf(sh[(rg +  4) * FI + k], wv, a1);
        a2 = fmaf(sh[(rg +  8) * FI + k], wv, a2);
        a3 = fmaf(sh[(rg + 12) * FI + k], wv, a3);
    }
    g_Wh[(size_t)(row0 + rg +  0) * FO + f] = a0;
    g_Wh[(size_t)(row0 + rg +  4) * FO + f] = a1;
    g_Wh[(size_t)(row0 + rg +  8) * FO + f] = a2;
    g_Wh[(size_t)(row0 + rg + 12) * FO + f] = a3;
}

// ---------------------------------------------------------------------------
// Kernel 2: s1 = Wh @ a[:64],  s2 = Wh @ a[64:]   (1 warp / row)
// ---------------------------------------------------------------------------
__global__ void __launch_bounds__(256) s_kernel(const float* __restrict__ a) {
    const int row  = blockIdx.x * 8 + (threadIdx.x >> 5);
    const int lane = threadIdx.x & 31;
    const float* wh = g_Wh + (size_t)row * FO;
    const float w0 = wh[lane], w1 = wh[lane + 32];
    float s1 = w0 * a[lane]      + w1 * a[lane + 32];
    float s2 = w0 * a[FO + lane] + w1 * a[FO + lane + 32];
    #pragma unroll
    for (int off = 16; off; off >>= 1) {
        s1 += __shfl_xor_sync(0xffffffffu, s1, off);
        s2 += __shfl_xor_sync(0xffffffffu, s2, off);
    }
    if (lane == 0) { g_s1[row] = s1; g_s2[row] = s2; }
}

// ---------------------------------------------------------------------------
// Kernel 3: fused masked-softmax attention + aggregation + ELU
//   out[b,i,:] = elu( (sum_j P_ij * Wh[b,j,:]) / (sum_j P_ij) )
//   P_ij = adj ? exp(lrelu(s1_i + s2_j)) : 0        (no max-sub needed; bounded logits)
// ---------------------------------------------------------------------------
__device__ __forceinline__ void prefetch_tile(
    int jt, int pq,
    const int* __restrict__ adjrow, const float* __restrict__ s2b,
    const float* __restrict__ whrow,
    int4 adjv[4], float4 s2v[4], float4 whv[4])
{
    const int j0 = jt * TJ;
    #pragma unroll
    for (int k = 0; k < 4; ++k) {
        const int jc = j0 + pq * 16 + k * 4;
        adjv[k] = *(const int4*)(adjrow + jc);
        s2v[k]  = *(const float4*)(s2b + jc);
        whv[k]  = *(const float4*)(whrow + (size_t)j0 * FO + k * 4);
    }
}

__global__ void __launch_bounds__(256, 2) gat_kernel(const int* __restrict__ adj,
                                                     float* __restrict__ out) {
    __shared__ float sP[TJ * TI];    // transposed: sP[j][i]   16 KB
    __shared__ float sWh[TJ * FO];   // sWh[j][f]              16 KB
    __shared__ float srow[TI];       // running row sums

    const int tid = threadIdx.x;
    const int b   = blockIdx.y;
    const int i0  = blockIdx.x * TI;

    const int pi = tid >> 2;   // 0..63: local i (adj) / local j (Wh)
    const int pq = tid & 3;    // 0..3 : 16-wide j quarter / 16-wide f quarter
    const int tx = tid & 15;   // matmul: feature group
    const int ty = tid >> 4;   // matmul: row group

    if (tid < TI) srow[tid] = 0.f;

    const float  s1i    = g_s1[b * NN + i0 + pi];
    const int*   adjrow = adj + ((size_t)b * NN + i0 + pi) * NN;
    const float* s2b    = g_s2 + b * NN;
    const float* whrow  = g_Wh + (size_t)b * NN * FO + (size_t)pi * FO + pq * 16;

    float acc[4][4];
    #pragma unroll
    for (int r = 0; r < 4; ++r)
        #pragma unroll
        for (int c = 0; c < 4; ++c) acc[r][c] = 0.f;

    int4   adjv[4];
    float4 s2v[4];
    float4 whv[4];
    prefetch_tile(0, pq, adjrow, s2b, whrow, adjv, s2v, whv);

    for (int jt = 0; jt < NT; ++jt) {
        // ---- phase A: P generation + Wh tile staging (uses prefetched regs)
        float rsum = 0.f;
        #pragma unroll
        for (int k = 0; k < 4; ++k) {
            const int jl = pq * 16 + k * 4;
            float t, e, p;
            t = s1i + s2v[k].x; e = __expf(fmaxf(t, LRALPHA * t));
            p = adjv[k].x ? e : 0.f; sP[(jl + 0) * TI + pi] = p; rsum += p;
            t = s1i + s2v[k].y; e = __expf(fmaxf(t, LRALPHA * t));
            p = adjv[k].y ? e : 0.f; sP[(jl + 1) * TI + pi] = p; rsum += p;
            t = s1i + s2v[k].z; e = __expf(fmaxf(t, LRALPHA * t));
            p = adjv[k].z ? e : 0.f; sP[(jl + 2) * TI + pi] = p; rsum += p;
            t = s1i + s2v[k].w; e = __expf(fmaxf(t, LRALPHA * t));
            p = adjv[k].w ? e : 0.f; sP[(jl + 3) * TI + pi] = p; rsum += p;
        }
        // reduce rowsum over the 4 adjacent lanes sharing pi
        rsum += __shfl_xor_sync(0xffffffffu, rsum, 1);
        rsum += __shfl_xor_sync(0xffffffffu, rsum, 2);
        if (pq == 0) srow[pi] += rsum;

        #pragma unroll
        for (int k = 0; k < 4; ++k)
            *(float4*)(sWh + pi * FO + pq * 16 + k * 4) = whv[k];

        __syncthreads();

        // ---- prefetch next tile (latency hidden under matmul)
        if (jt + 1 < NT)
            prefetch_tile(jt + 1, pq, adjrow, s2b, whrow, adjv, s2v, whv);

        // ---- phase B: acc += P_tile^T-layout GEMM
        #pragma unroll 8
        for (int jj = 0; jj < TJ; ++jj) {
            const float4 pv = *(const float4*)(sP  + jj * TI + ty * 4);
            const float4 wv = *(const float4*)(sWh + jj * FO + tx * 4);
            acc[0][0] = fmaf(pv.x, wv.x, acc[0][0]);
            acc[0][1] = fmaf(pv.x, wv.y, acc[0][1]);
            acc[0][2] = fmaf(pv.x, wv.z, acc[0][2]);
            acc[0][3] = fmaf(pv.x, wv.w, acc[0][3]);
            acc[1][0] = fmaf(pv.y, wv.x, acc[1][0]);
            acc[1][1] = fmaf(pv.y, wv.y, acc[1][1]);
            acc[1][2] = fmaf(pv.y, wv.z, acc[1][2]);
            acc[1][3] = fmaf(pv.y, wv.w, acc[1][3]);
            acc[2][0] = fmaf(pv.z, wv.x, acc[2][0]);
            acc[2][1] = fmaf(pv.z, wv.y, acc[2][1]);
            acc[2][2] = fmaf(pv.z, wv.z, acc[2][2]);
            acc[2][3] = fmaf(pv.z, wv.w, acc[2][3]);
            acc[3][0] = fmaf(pv.w, wv.x, acc[3][0]);
            acc[3][1] = fmaf(pv.w, wv.y, acc[3][1]);
            acc[3][2] = fmaf(pv.w, wv.z, acc[3][2]);
            acc[3][3] = fmaf(pv.w, wv.w, acc[3][3]);
        }
        __syncthreads();
    }

    // ---- epilogue: normalize + ELU + store
    #pragma unroll
    for (int r = 0; r < 4; ++r) {
        const int il = ty * 4 + r;
        const float inv = 1.0f / srow[il];
        float4 o;
        float v;
        v = acc[r][0] * inv; o.x = (v > 0.f) ? v : expm1f(v);
        v = acc[r][1] * inv; o.y = (v > 0.f) ? v : expm1f(v);
        v = acc[r][2] * inv; o.z = (v > 0.f) ? v : expm1f(v);
        v = acc[r][3] * inv; o.w = (v > 0.f) ? v : expm1f(v);
        *(float4*)(out + ((size_t)(b * NN) + i0 + il) * FO + tx * 4) = o;
    }
}

// ---------------------------------------------------------------------------
extern "C" void kernel_launch(void* const* d_in, const int* in_sizes, int n_in,
                              void* d_out, int out_size) {
    const float* h   = (const float*)d_in[0];   // [8,2048,128] f32
    const float* W   = (const float*)d_in[1];   // [128,64] f32
    const float* a   = (const float*)d_in[2];   // [128,1] f32
    const int*   adj = (const int*)d_in[3];     // [8,2048,2048] i32
    float* out = (float*)d_out;                 // [8,2048,64] f32

    wh_kernel<<<BB * NN / 16, 256>>>(h, W);
    s_kernel<<<BB * NN / 8, 256>>>(a);
    dim3 grid(NN / TI, BB);
    gat_kernel<<<grid, 256>>>(adj, out);
}

// round 6
// speedup vs baseline: 1.8677x; 1.8677x over previous
#include <cuda_runtime.h>
#include <cuda_bf16.h>
#include <cstdint>
#include <math.h>

#define BB 8
#define NN 2048
#define FI 128
#define FO 64
#define KT 64
#define TI 64
#define NCHUNK (NN / KT)

// ---------------- scratch (static device arrays: allocation-free) ----------
__device__ __nv_bfloat16 g_Wh_hi[(size_t)BB * NN * FO];  // [row][f] 2MB
__device__ __nv_bfloat16 g_Wh_lo[(size_t)BB * NN * FO];  // 2MB
__device__ float4 g_srow[BB * NN];   // (-s1, exp(s1), exp(0.2 s1), 0)
__device__ float4 g_scol[BB * NN];   // (s2, exp(s2), exp(0.2 s2), 0)

// ---------------- helpers ---------------------------------------------------
__device__ __forceinline__ uint32_t smem_u32(const void* p) {
    uint32_t a;
    asm("{ .reg .u64 t; cvta.to.shared.u64 t, %1; cvt.u32.u64 %0, t; }" : "=r"(a) : "l"(p));
    return a;
}

__device__ __forceinline__ void mma16816(float* c, uint32_t a0, uint32_t a1,
                                         uint32_t a2, uint32_t a3,
                                         uint32_t b0, uint32_t b1) {
    asm volatile("mma.sync.aligned.m16n8k16.row.col.f32.bf16.bf16.f32 "
                 "{%0,%1,%2,%3}, {%4,%5,%6,%7}, {%8,%9}, {%0,%1,%2,%3};"
                 : "+f"(c[0]), "+f"(c[1]), "+f"(c[2]), "+f"(c[3])
                 : "r"(a0), "r"(a1), "r"(a2), "r"(a3), "r"(b0), "r"(b1));
}

__device__ __forceinline__ void ldsm4t(uint32_t* r, uint32_t addr) {
    asm volatile("ldmatrix.sync.aligned.m8n8.x4.trans.shared.b16 {%0,%1,%2,%3}, [%4];"
                 : "=r"(r[0]), "=r"(r[1]), "=r"(r[2]), "=r"(r[3]) : "r"(addr));
}

__device__ __forceinline__ void cpasync16(uint32_t dst, const void* src) {
    asm volatile("cp.async.ca.shared.global [%0], [%1], 16;" :: "r"(dst), "l"(src));
}

__device__ __forceinline__ uint32_t packbf2(float x, float y) {
    __nv_bfloat162 v = __float22bfloat162_rn(make_float2(x, y));
    return *(uint32_t*)&v;
}

// residual after bf16 truncation of the pair packed in w (low=first elem)
__device__ __forceinline__ uint32_t packlo(uint32_t w, float x, float y) {
    const float hx = __uint_as_float(w << 16);
    const float hy = __uint_as_float(w & 0xFFFF0000u);
    return packbf2(x - hx, y - hy);
}

__device__ __forceinline__ float f4c(const float4& v, int k) {
    return k == 0 ? v.x : (k == 1 ? v.y : (k == 2 ? v.z : v.w));
}

// p = adj ? (s1+s2>0 ? E1*E2 : F1*F2) : 0
// rp = (-s1, E1, F1, _)    sc = (s2, E2, F2, _)
__device__ __forceinline__ float pval(const float4& rp, const float4& sc, int adjv) {
    const bool gt = sc.x > rp.x;
    const float e1 = gt ? rp.y : rp.z;
    const float e2 = gt ? sc.y : sc.z;
    return adjv ? e1 * e2 : 0.f;
}

// ---------------------------------------------------------------------------
// Kernel 1: Wh = h @ W ; emits g_Wh_{hi,lo} ([row][f], bf16 split) + per-node
// attention tables g_srow / g_scol. 128 rows/block, thread tile 4 rows x 8 f.
// ---------------------------------------------------------------------------
__global__ void __launch_bounds__(256, 2) wh_kernel(const float* __restrict__ h,
                                                    const float* __restrict__ W,
                                                    const float* __restrict__ a) {
    extern __shared__ __align__(16) unsigned char smem_raw[];
    float4* sh4 = (float4*)smem_raw;                     // 128 x 128 f32 = 64KB
    float4* sW4 = (float4*)(smem_raw + 65536);           // 128 x 64 f32 = 32KB

    const int tid  = threadIdx.x;
    const int row0 = blockIdx.x * 128;

    const float4* hsrc = (const float4*)(h + (size_t)row0 * FI);
    #pragma unroll 4
    for (int i = tid; i < 128 * FI / 4; i += 256) sh4[i] = hsrc[i];
    const float4* wsrc = (const float4*)W;
    #pragma unroll 2
    for (int i = tid; i < FI * FO / 4; i += 256) sW4[i] = wsrc[i];
    __syncthreads();

    const int fg   = tid & 7;    // feature group: f0 = fg*8
    const int rowg = tid >> 3;   // 0..31: rows rowg*4 .. +3

    float acc[4][8];
    #pragma unroll
    for (int r = 0; r < 4; ++r)
        #pragma unroll
        for (int c = 0; c < 8; ++c) acc[r][c] = 0.f;

    #pragma unroll 2
    for (int k4 = 0; k4 < FI / 4; ++k4) {
        float4 hv[4];
        #pragma unroll
        for (int r = 0; r < 4; ++r) hv[r] = sh4[(rowg * 4 + r) * (FI / 4) + k4];
        #pragma unroll
        for (int kk = 0; kk < 4; ++kk) {
            const float4 wa = sW4[(k4 * 4 + kk) * 16 + fg * 2];
            const float4 wb = sW4[(k4 * 4 + kk) * 16 + fg * 2 + 1];
            #pragma unroll
            for (int r = 0; r < 4; ++r) {
                const float hk = f4c(hv[r], kk);
                acc[r][0] = fmaf(hk, wa.x, acc[r][0]);
                acc[r][1] = fmaf(hk, wa.y, acc[r][1]);
                acc[r][2] = fmaf(hk, wa.z, acc[r][2]);
                acc[r][3] = fmaf(hk, wa.w, acc[r][3]);
                acc[r][4] = fmaf(hk, wb.x, acc[r][4]);
                acc[r][5] = fmaf(hk, wb.y, acc[r][5]);
                acc[r][6] = fmaf(hk, wb.z, acc[r][6]);
                acc[r][7] = fmaf(hk, wb.w, acc[r][7]);
            }
        }
    }

    // ---- s1/s2 partials over this thread's 8 features, reduce over fg lanes
    const float4* a4 = (const float4*)a;
    const float4 a1a = a4[fg * 2], a1b = a4[fg * 2 + 1];
    const float4 a2a = a4[16 + fg * 2], a2b = a4[16 + fg * 2 + 1];
    float s1p[4], s2p[4];
    #pragma unroll
    for (int r = 0; r < 4; ++r) {
        s1p[r] = acc[r][0] * a1a.x + acc[r][1] * a1a.y + acc[r][2] * a1a.z + acc[r][3] * a1a.w
               + acc[r][4] * a1b.x + acc[r][5] * a1b.y + acc[r][6] * a1b.z + acc[r][7] * a1b.w;
        s2p[r] = acc[r][0] * a2a.x + acc[r][1] * a2a.y + acc[r][2] * a2a.z + acc[r][3] * a2a.w
               + acc[r][4] * a2b.x + acc[r][5] * a2b.y + acc[r][6] * a2b.z + acc[r][7] * a2b.w;
    }
    #pragma unroll
    for (int off = 1; off < 8; off <<= 1)
        #pragma unroll
        for (int r = 0; r < 4; ++r) {
            s1p[r] += __shfl_xor_sync(0xffffffffu, s1p[r], off);
            s2p[r] += __shfl_xor_sync(0xffffffffu, s2p[r], off);
        }
    if (fg == 0) {
        #pragma unroll
        for (int r = 0; r < 4; ++r) {
            const int row = row0 + rowg * 4 + r;
            const float s1 = s1p[r], s2 = s2p[r];
            g_srow[row] = make_float4(-s1, __expf(s1), __expf(0.2f * s1), 0.f);
            g_scol[row] = make_float4(s2, __expf(s2), __expf(0.2f * s2), 0.f);
        }
    }

    // ---- bf16 hi/lo planes, natural [row][f] layout
    #pragma unroll
    for (int r = 0; r < 4; ++r) {
        const int row = row0 + rowg * 4 + r;
        uint32_t hw[4], lw[4];
        #pragma unroll
        for (int cp = 0; cp < 4; ++cp) {
            const float v0 = acc[r][cp * 2], v1 = acc[r][cp * 2 + 1];
            __nv_bfloat162 hp = __float22bfloat162_rn(make_float2(v0, v1));
            const float l0 = v0 - __bfloat162float(hp.x);
            const float l1 = v1 - __bfloat162float(hp.y);
            __nv_bfloat162 lp = __float22bfloat162_rn(make_float2(l0, l1));
            hw[cp] = *(uint32_t*)&hp;
            lw[cp] = *(uint32_t*)&lp;
        }
        const size_t idx = (size_t)row * FO + fg * 8;
        *(uint4*)(g_Wh_hi + idx) = make_uint4(hw[0], hw[1], hw[2], hw[3]);
        *(uint4*)(g_Wh_lo + idx) = make_uint4(lw[0], lw[1], lw[2], lw[3]);
    }
}

// ---------------------------------------------------------------------------
// Kernel 2: fused GAT attention via mma.sync bf16.
// P hi/lo split (A planes, in-register), Wh hi/lo split (B planes in smem).
// num = Ph*Bh + Ph*Bl + Pl*Bh.
// CTA: 64 i-rows x 64 f. Warps 0-3: rows w*16..+15 / cols 0-31;
// warps 4-7: same rows, cols 32-63 (column twins).
// ---------------------------------------------------------------------------
#define SB_STRIDE 144            // 64 bf16 + 16B pad
#define SB_PLANE  (64 * SB_STRIDE)
#define OFF_SCOL  0
#define OFF_SB    32768
#define OFF_SROW  (OFF_SB + 4 * SB_PLANE)   // 69632
#define GAT_SMEM  (OFF_SROW + 256)          // 69888

__device__ __forceinline__ void stage_chunk(uint32_t sb, int buf, int rowbase, int tid) {
    #pragma unroll
    for (int q = 0; q < 4; ++q) {
        const int id    = tid + q * 256;     // 0..1023
        const int plane = id >> 9;
        const int rem   = id & 511;
        const int row   = rem >> 3;
        const int c16   = rem & 7;
        const __nv_bfloat16* src =
            (plane ? g_Wh_lo : g_Wh_hi) + (size_t)(rowbase + row) * FO + c16 * 8;
        const uint32_t dst = sb + (buf * 2 + plane) * SB_PLANE + row * SB_STRIDE + c16 * 16;
        cpasync16(dst, src);
    }
}

__global__ void __launch_bounds__(256, 2) gat_kernel(const int* __restrict__ adj,
                                                     float* __restrict__ out) {
    extern __shared__ __align__(16) unsigned char smem_raw[];
    float4* scol = (float4*)smem_raw;                       // 32KB
    float*  srow = (float*)(smem_raw + OFF_SROW);
    const uint32_t sb = smem_u32(smem_raw) + OFF_SB;

    const int tid  = threadIdx.x;
    const int lane = tid & 31;
    const int wid  = tid >> 5;
    const int b    = blockIdx.y;
    const int i0   = blockIdx.x * TI;

    const int mb = (wid & 3) * 16;      // warp row base (local, 0..48)
    const int nb = (wid >> 2) * 32;     // warp col base (0 or 32)
    const int lrl = mb + (lane >> 2);   // local row (lo)
    const int lrh = lrl + 8;
    const int qc  = (lane & 3) * 2;     // k-pair base within 16

    // preload scol for batch b (f32 tables: exact P)
    {
        const float4* src = (const float4*)(g_scol + b * NN);
        #pragma unroll 2
        for (int i = tid; i < NN; i += 256) scol[i] = src[i];
    }

    const float4 rp_lo = g_srow[b * NN + i0 + lrl];
    const float4 rp_hi = g_srow[b * NN + i0 + lrh];
    const int* adjl = adj + (size_t)(b * NN + i0 + lrl) * NN;
    const int* adjh = adj + (size_t)(b * NN + i0 + lrh) * NN;

    stage_chunk(sb, 0, b * NN, tid);
    asm volatile("cp.async.commit_group;" ::: "memory");
    __syncthreads();   // scol visible

    float acc[4][4];
    #pragma unroll
    for (int nt = 0; nt < 4; ++nt)
        #pragma unroll
        for (int k = 0; k < 4; ++k) acc[nt][k] = 0.f;
    float rsum_lo = 0.f, rsum_hi = 0.f;

    const int lrow = (lane & 7) + (lane & 8);       // ldmatrix row 0..15
    const int lcol = (lane >> 4) << 3;              // 0 or 8

    #pragma unroll 1
    for (int t = 0; t < NCHUNK; ++t) {
        if (t + 1 < NCHUNK) {
            stage_chunk(sb, (t + 1) & 1, b * NN + (t + 1) * KT, tid);
            asm volatile("cp.async.commit_group;" ::: "memory");
            asm volatile("cp.async.wait_group 1;" ::: "memory");
        } else {
            asm volatile("cp.async.wait_group 0;" ::: "memory");
        }
        __syncthreads();   // chunk t landed everywhere

        const uint32_t bufh = sb + ((t & 1) * 2 + 0) * SB_PLANE;
        const uint32_t bufl = bufh + SB_PLANE;
        const int j0 = t * KT;

        #pragma unroll
        for (int kt = 0; kt < 4; ++kt) {
            const int c0 = j0 + kt * 16 + qc;
            const float4 sc0 = scol[c0];
            const float4 sc1 = scol[c0 + 1];
            const float4 sc8 = scol[c0 + 8];
            const float4 sc9 = scol[c0 + 9];
            const int2 al0 = *(const int2*)(adjl + c0);
            const int2 al8 = *(const int2*)(adjl + c0 + 8);
            const int2 ah0 = *(const int2*)(adjh + c0);
            const int2 ah8 = *(const int2*)(adjh + c0 + 8);

            const float pl0 = pval(rp_lo, sc0, al0.x);
            const float pl1 = pval(rp_lo, sc1, al0.y);
            const float pl8 = pval(rp_lo, sc8, al8.x);
            const float pl9 = pval(rp_lo, sc9, al8.y);
            const float ph0 = pval(rp_hi, sc0, ah0.x);
            const float ph1 = pval(rp_hi, sc1, ah0.y);
            const float ph8 = pval(rp_hi, sc8, ah8.x);
            const float ph9 = pval(rp_hi, sc9, ah8.y);

            rsum_lo += (pl0 + pl1) + (pl8 + pl9);
            rsum_hi += (ph0 + ph1) + (ph8 + ph9);

            // A fragments: hi plane + residual (lo) plane
            const uint32_t a0 = packbf2(pl0, pl1);
            const uint32_t a1 = packbf2(ph0, ph1);
            const uint32_t a2 = packbf2(pl8, pl9);
            const uint32_t a3 = packbf2(ph8, ph9);
            const uint32_t e0 = packlo(a0, pl0, pl1);
            const uint32_t e1 = packlo(a1, ph0, ph1);
            const uint32_t e2 = packlo(a2, pl8, pl9);
            const uint32_t e3 = packlo(a3, ph8, ph9);

            // B fragments: hi & lo planes, this warp's 32 cols
            const uint32_t rowoff = (uint32_t)(kt * 16 + lrow) * SB_STRIDE + (nb + lcol) * 2;
            uint32_t bh[8], bl[8];
            ldsm4t(bh,     bufh + rowoff);
            ldsm4t(bh + 4, bufh + rowoff + 32);
            ldsm4t(bl,     bufl + rowoff);
            ldsm4t(bl + 4, bufl + rowoff + 32);

            #pragma unroll
            for (int nt = 0; nt < 4; ++nt) {
                mma16816(acc[nt], a0, a1, a2, a3, bh[nt * 2], bh[nt * 2 + 1]);
                mma16816(acc[nt], a0, a1, a2, a3, bl[nt * 2], bl[nt * 2 + 1]);
                mma16816(acc[nt], e0, e1, e2, e3, bh[nt * 2], bh[nt * 2 + 1]);
            }
        }
        __syncthreads();   // all reads of buf t done before it is re-staged
    }

    // ---- rowsums (twins compute identical sums; warps 0-3 publish)
    rsum_lo += __shfl_xor_sync(0xffffffffu, rsum_lo, 1);
    rsum_lo += __shfl_xor_sync(0xffffffffu, rsum_lo, 2);
    rsum_hi += __shfl_xor_sync(0xffffffffu, rsum_hi, 1);
    rsum_hi += __shfl_xor_sync(0xffffffffu, rsum_hi, 2);
    if (wid < 4 && (lane & 3) == 0) {
        srow[lrl] = rsum_lo;
        srow[lrh] = rsum_hi;
    }
    __syncthreads();

    const float invl = 1.0f / srow[lrl];
    const float invh = 1.0f / srow[lrh];
    float* outl = out + (size_t)(b * NN + i0 + lrl) * FO;
    float* outh = out + (size_t)(b * NN + i0 + lrh) * FO;
    #pragma unroll
    for (int nt = 0; nt < 4; ++nt) {
        const int cb = nb + nt * 8 + qc;
        float2 o;
        float v;
        v = acc[nt][0] * invl; o.x = (v > 0.f) ? v : expm1f(v);
        v = acc[nt][1] * invl; o.y = (v > 0.f) ? v : expm1f(v);
        *(float2*)(outl + cb) = o;
        v = acc[nt][2] * invh; o.x = (v > 0.f) ? v : expm1f(v);
        v = acc[nt][3] * invh; o.y = (v > 0.f) ? v : expm1f(v);
        *(float2*)(outh + cb) = o;
    }
}

// ---------------------------------------------------------------------------
extern "C" void kernel_launch(void* const* d_in, const int* in_sizes, int n_in,
                              void* d_out, int out_size) {
    const float* h   = (const float*)d_in[0];   // [8,2048,128] f32
    const float* W   = (const float*)d_in[1];   // [128,64] f32
    const float* a   = (const float*)d_in[2];   // [128,1] f32
    const int*   adj = (const int*)d_in[3];     // [8,2048,2048] i32
    float* out = (float*)d_out;                 // [8,2048,64] f32

    cudaFuncSetAttribute(wh_kernel, cudaFuncAttributeMaxDynamicSharedMemorySize, 98304);
    cudaFuncSetAttribute(gat_kernel, cudaFuncAttributeMaxDynamicSharedMemorySize, GAT_SMEM);

    wh_kernel<<<BB * NN / 128, 256, 98304>>>(h, W, a);
    dim3 grid(NN / TI, BB);
    gat_kernel<<<grid, 256, GAT_SMEM>>>(adj, out);
}

// round 7
// speedup vs baseline: 2.3209x; 1.2427x over previous
#include <cuda_runtime.h>
#include <cuda_bf16.h>
#include <cuda_fp16.h>
#include <cstdint>
#include <math.h>

#define BB 8
#define NN 2048
#define FI 128
#define FO 64
#define KT 64
#define TI 64
#define NCHUNK (NN / KT)

// ---------------- scratch (static device arrays: allocation-free) ----------
__device__ __half g_Wh_h[(size_t)BB * NN * FO];  // [row][f] 2MB, fp16
__device__ float4 g_srow[BB * NN];   // (-s1, exp(s1), exp(0.2 s1), 0)
__device__ float4 g_scol[BB * NN];   // (s2, exp(s2), exp(0.2 s2), 0)

// ---------------- helpers ---------------------------------------------------
__device__ __forceinline__ uint32_t smem_u32(const void* p) {
    uint32_t a;
    asm("{ .reg .u64 t; cvta.to.shared.u64 t, %1; cvt.u32.u64 %0, t; }" : "=r"(a) : "l"(p));
    return a;
}

__device__ __forceinline__ void mma16816(float* c, uint32_t a0, uint32_t a1,
                                         uint32_t a2, uint32_t a3,
                                         uint32_t b0, uint32_t b1) {
    asm volatile("mma.sync.aligned.m16n8k16.row.col.f32.f16.f16.f32 "
                 "{%0,%1,%2,%3}, {%4,%5,%6,%7}, {%8,%9}, {%0,%1,%2,%3};"
                 : "+f"(c[0]), "+f"(c[1]), "+f"(c[2]), "+f"(c[3])
                 : "r"(a0), "r"(a1), "r"(a2), "r"(a3), "r"(b0), "r"(b1));
}

__device__ __forceinline__ void ldsm4t(uint32_t* r, uint32_t addr) {
    asm volatile("ldmatrix.sync.aligned.m8n8.x4.trans.shared.b16 {%0,%1,%2,%3}, [%4];"
                 : "=r"(r[0]), "=r"(r[1]), "=r"(r[2]), "=r"(r[3]) : "r"(addr));
}

__device__ __forceinline__ void cpasync16(uint32_t dst, const void* src) {
    asm volatile("cp.async.ca.shared.global [%0], [%1], 16;" :: "r"(dst), "l"(src));
}

__device__ __forceinline__ uint32_t packhf2(float x, float y) {
    __half2 v = __float22half2_rn(make_float2(x, y));
    return *(uint32_t*)&v;
}

__device__ __forceinline__ float f4c(const float4& v, int k) {
    return k == 0 ? v.x : (k == 1 ? v.y : (k == 2 ? v.z : v.w));
}

// p = adj ? (s1+s2>0 ? E1*E2 : F1*F2) : 0
// rp = (-s1, E1, F1, _)    sc = (s2, E2, F2, _)
__device__ __forceinline__ float pval(const float4& rp, const float4& sc, int adjv) {
    const bool gt = sc.x > rp.x;
    const float e1 = gt ? rp.y : rp.z;
    const float e2 = gt ? sc.y : sc.z;
    return adjv ? e1 * e2 : 0.f;
}

// ---------------------------------------------------------------------------
// Kernel 1: Wh = h @ W ; emits g_Wh_h ([row][f], fp16) + per-node attention
// tables g_srow / g_scol. 128 rows/block, thread tile 4 rows x 8 features.
// ---------------------------------------------------------------------------
__global__ void __launch_bounds__(256, 2) wh_kernel(const float* __restrict__ h,
                                                    const float* __restrict__ W,
                                                    const float* __restrict__ a) {
    extern __shared__ __align__(16) unsigned char smem_raw[];
    float4* sh4 = (float4*)smem_raw;                     // 128 x 128 f32 = 64KB
    float4* sW4 = (float4*)(smem_raw + 65536);           // 128 x 64 f32 = 32KB

    const int tid  = threadIdx.x;
    const int row0 = blockIdx.x * 128;

    const float4* hsrc = (const float4*)(h + (size_t)row0 * FI);
    #pragma unroll 4
    for (int i = tid; i < 128 * FI / 4; i += 256) sh4[i] = hsrc[i];
    const float4* wsrc = (const float4*)W;
    #pragma unroll 2
    for (int i = tid; i < FI * FO / 4; i += 256) sW4[i] = wsrc[i];
    __syncthreads();

    const int fg   = tid & 7;    // feature group: f0 = fg*8
    const int rowg = tid >> 3;   // 0..31: rows rowg*4 .. +3

    float acc[4][8];
    #pragma unroll
    for (int r = 0; r < 4; ++r)
        #pragma unroll
        for (int c = 0; c < 8; ++c) acc[r][c] = 0.f;

    #pragma unroll 2
    for (int k4 = 0; k4 < FI / 4; ++k4) {
        float4 hv[4];
        #pragma unroll
        for (int r = 0; r < 4; ++r) hv[r] = sh4[(rowg * 4 + r) * (FI / 4) + k4];
        #pragma unroll
        for (int kk = 0; kk < 4; ++kk) {
            const float4 wa = sW4[(k4 * 4 + kk) * 16 + fg * 2];
            const float4 wb = sW4[(k4 * 4 + kk) * 16 + fg * 2 + 1];
            #pragma unroll
            for (int r = 0; r < 4; ++r) {
                const float hk = f4c(hv[r], kk);
                acc[r][0] = fmaf(hk, wa.x, acc[r][0]);
                acc[r][1] = fmaf(hk, wa.y, acc[r][1]);
                acc[r][2] = fmaf(hk, wa.z, acc[r][2]);
                acc[r][3] = fmaf(hk, wa.w, acc[r][3]);
                acc[r][4] = fmaf(hk, wb.x, acc[r][4]);
                acc[r][5] = fmaf(hk, wb.y, acc[r][5]);
                acc[r][6] = fmaf(hk, wb.z, acc[r][6]);
                acc[r][7] = fmaf(hk, wb.w, acc[r][7]);
            }
        }
    }

    // ---- s1/s2 partials over this thread's 8 features, reduce over fg lanes
    const float4* a4 = (const float4*)a;
    const float4 a1a = a4[fg * 2], a1b = a4[fg * 2 + 1];
    const float4 a2a = a4[16 + fg * 2], a2b = a4[16 + fg * 2 + 1];
    float s1p[4], s2p[4];
    #pragma unroll
    for (int r = 0; r < 4; ++r) {
        s1p[r] = acc[r][0] * a1a.x + acc[r][1] * a1a.y + acc[r][2] * a1a.z + acc[r][3] * a1a.w
               + acc[r][4] * a1b.x + acc[r][5] * a1b.y + acc[r][6] * a1b.z + acc[r][7] * a1b.w;
        s2p[r] = acc[r][0] * a2a.x + acc[r][1] * a2a.y + acc[r][2] * a2a.z + acc[r][3] * a2a.w
               + acc[r][4] * a2b.x + acc[r][5] * a2b.y + acc[r][6] * a2b.z + acc[r][7] * a2b.w;
    }
    #pragma unroll
    for (int off = 1; off < 8; off <<= 1)
        #pragma unroll
        for (int r = 0; r < 4; ++r) {
            s1p[r] += __shfl_xor_sync(0xffffffffu, s1p[r], off);
            s2p[r] += __shfl_xor_sync(0xffffffffu, s2p[r], off);
        }
    if (fg == 0) {
        #pragma unroll
        for (int r = 0; r < 4; ++r) {
            const int row = row0 + rowg * 4 + r;
            const float s1 = s1p[r], s2 = s2p[r];
            g_srow[row] = make_float4(-s1, __expf(s1), __expf(0.2f * s1), 0.f);
            g_scol[row] = make_float4(s2, __expf(s2), __expf(0.2f * s2), 0.f);
        }
    }

    // ---- fp16 plane, natural [row][f] layout
    #pragma unroll
    for (int r = 0; r < 4; ++r) {
        const int row = row0 + rowg * 4 + r;
        uint32_t hw[4];
        #pragma unroll
        for (int cp = 0; cp < 4; ++cp)
            hw[cp] = packhf2(acc[r][cp * 2], acc[r][cp * 2 + 1]);
        *(uint4*)(g_Wh_h + (size_t)row * FO + fg * 8) = make_uint4(hw[0], hw[1], hw[2], hw[3]);
    }
}

// ---------------------------------------------------------------------------
// Kernel 2: fused GAT attention via mma.sync fp16 (single plane).
// CTA: 64 i-rows x 64 f. Warps 0-3: rows w*16..+15 / cols 0-31;
// warps 4-7: same rows, cols 32-63 (column twins).
// ---------------------------------------------------------------------------
#define SB_STRIDE 144            // 64 fp16 + 16B pad
#define SB_PLANE  (64 * SB_STRIDE)
#define OFF_SB    32768
#define OFF_SROW  (OFF_SB + 2 * SB_PLANE)   // 51200
#define GAT_SMEM  (OFF_SROW + 256)          // 51456

__device__ __forceinline__ void stage_chunk(uint32_t sb, int buf, int rowbase, int tid) {
    #pragma unroll
    for (int q = 0; q < 2; ++q) {
        const int id  = tid + q * 256;     // 0..511
        const int row = id >> 3;
        const int c16 = id & 7;
        const __half* src = g_Wh_h + (size_t)(rowbase + row) * FO + c16 * 8;
        const uint32_t dst = sb + buf * SB_PLANE + row * SB_STRIDE + c16 * 16;
        cpasync16(dst, src);
    }
}

__global__ void __launch_bounds__(256, 2) gat_kernel(const int* __restrict__ adj,
                                                     float* __restrict__ out) {
    extern __shared__ __align__(16) unsigned char smem_raw[];
    float4* scol = (float4*)smem_raw;                       // 32KB
    float*  srow = (float*)(smem_raw + OFF_SROW);
    const uint32_t sb = smem_u32(smem_raw) + OFF_SB;

    const int tid  = threadIdx.x;
    const int lane = tid & 31;
    const int wid  = tid >> 5;
    const int b    = blockIdx.y;
    const int i0   = blockIdx.x * TI;

    const int mb = (wid & 3) * 16;      // warp row base (local, 0..48)
    const int nb = (wid >> 2) * 32;     // warp col base (0 or 32)
    const int lrl = mb + (lane >> 2);   // local row (lo)
    const int lrh = lrl + 8;
    const int qc  = (lane & 3) * 2;     // k-pair base within 16

    // preload scol for batch b (f32 tables: exact P)
    {
        const float4* src = (const float4*)(g_scol + b * NN);
        #pragma unroll 2
        for (int i = tid; i < NN; i += 256) scol[i] = src[i];
    }

    const float4 rp_lo = g_srow[b * NN + i0 + lrl];
    const float4 rp_hi = g_srow[b * NN + i0 + lrh];
    const int* adjl = adj + (size_t)(b * NN + i0 + lrl) * NN;
    const int* adjh = adj + (size_t)(b * NN + i0 + lrh) * NN;

    stage_chunk(sb, 0, b * NN, tid);
    asm volatile("cp.async.commit_group;" ::: "memory");
    __syncthreads();   // scol visible

    float acc[4][4];
    #pragma unroll
    for (int nt = 0; nt < 4; ++nt)
        #pragma unroll
        for (int k = 0; k < 4; ++k) acc[nt][k] = 0.f;
    float rsum_lo = 0.f, rsum_hi = 0.f;

    const int lrow = (lane & 7) + (lane & 8);       // ldmatrix row 0..15
    const int lcol = (lane >> 4) << 3;              // 0 or 8

    #pragma unroll 1
    for (int t = 0; t < NCHUNK; ++t) {
        if (t + 1 < NCHUNK) {
            stage_chunk(sb, (t + 1) & 1, b * NN + (t + 1) * KT, tid);
            asm volatile("cp.async.commit_group;" ::: "memory");
            asm volatile("cp.async.wait_group 1;" ::: "memory");
        } else {
            asm volatile("cp.async.wait_group 0;" ::: "memory");
        }
        __syncthreads();   // chunk t landed everywhere

        const uint32_t bufh = sb + (t & 1) * SB_PLANE;
        const int j0 = t * KT;

        #pragma unroll
        for (int kt = 0; kt < 4; ++kt) {
            const int c0 = j0 + kt * 16 + qc;
            const float4 sc0 = scol[c0];
            const float4 sc1 = scol[c0 + 1];
            const float4 sc8 = scol[c0 + 8];
            const float4 sc9 = scol[c0 + 9];
            const int2 al0 = *(const int2*)(adjl + c0);
            const int2 al8 = *(const int2*)(adjl + c0 + 8);
            const int2 ah0 = *(const int2*)(adjh + c0);
            const int2 ah8 = *(const int2*)(adjh + c0 + 8);

            const float pl0 = pval(rp_lo, sc0, al0.x);
            const float pl1 = pval(rp_lo, sc1, al0.y);
            const float pl8 = pval(rp_lo, sc8, al8.x);
            const float pl9 = pval(rp_lo, sc9, al8.y);
            const float ph0 = pval(rp_hi, sc0, ah0.x);
            const float ph1 = pval(rp_hi, sc1, ah0.y);
            const float ph8 = pval(rp_hi, sc8, ah8.x);
            const float ph9 = pval(rp_hi, sc9, ah8.y);

            rsum_lo += (pl0 + pl1) + (pl8 + pl9);
            rsum_hi += (ph0 + ph1) + (ph8 + ph9);

            // A fragments (fp16)
            const uint32_t a0 = packhf2(pl0, pl1);
            const uint32_t a1 = packhf2(ph0, ph1);
            const uint32_t a2 = packhf2(pl8, pl9);
            const uint32_t a3 = packhf2(ph8, ph9);

            // B fragments: this warp's 32 cols
            const uint32_t rowoff = (uint32_t)(kt * 16 + lrow) * SB_STRIDE + (nb + lcol) * 2;
            uint32_t bh[8];
            ldsm4t(bh,     bufh + rowoff);
            ldsm4t(bh + 4, bufh + rowoff + 32);

            #pragma unroll
            for (int nt = 0; nt < 4; ++nt)
                mma16816(acc[nt], a0, a1, a2, a3, bh[nt * 2], bh[nt * 2 + 1]);
        }
        __syncthreads();   // all reads of buf t done before it is re-staged
    }

    // ---- rowsums (twins compute identical sums; warps 0-3 publish)
    rsum_lo += __shfl_xor_sync(0xffffffffu, rsum_lo, 1);
    rsum_lo += __shfl_xor_sync(0xffffffffu, rsum_lo, 2);
    rsum_hi += __shfl_xor_sync(0xffffffffu, rsum_hi, 1);
    rsum_hi += __shfl_xor_sync(0xffffffffu, rsum_hi, 2);
    if (wid < 4 && (lane & 3) == 0) {
        srow[lrl] = rsum_lo;
        srow[lrh] = rsum_hi;
    }
    __syncthreads();

    const float invl = 1.0f / srow[lrl];
    const float invh = 1.0f / srow[lrh];
    float* outl = out + (size_t)(b * NN + i0 + lrl) * FO;
    float* outh = out + (size_t)(b * NN + i0 + lrh) * FO;
    #pragma unroll
    for (int nt = 0; nt < 4; ++nt) {
        const int cb = nb + nt * 8 + qc;
        float2 o;
        float v;
        v = acc[nt][0] * invl; o.x = (v > 0.f) ? v : expm1f(v);
        v = acc[nt][1] * invl; o.y = (v > 0.f) ? v : expm1f(v);
        *(float2*)(outl + cb) = o;
        v = acc[nt][2] * invh; o.x = (v > 0.f) ? v : expm1f(v);
        v = acc[nt][3] * invh; o.y = (v > 0.f) ? v : expm1f(v);
        *(float2*)(outh + cb) = o;
    }
}

// ---------------------------------------------------------------------------
extern "C" void kernel_launch(void* const* d_in, const int* in_sizes, int n_in,
                              void* d_out, int out_size) {
    const float* h   = (const float*)d_in[0];   // [8,2048,128] f32
    const float* W   = (const float*)d_in[1];   // [128,64] f32
    const float* a   = (const float*)d_in[2];   // [128,1] f32
    const int*   adj = (const int*)d_in[3];     // [8,2048,2048] i32
    float* out = (float*)d_out;                 // [8,2048,64] f32

    cudaFuncSetAttribute(wh_kernel, cudaFuncAttributeMaxDynamicSharedMemorySize, 98304);
    cudaFuncSetAttribute(gat_kernel, cudaFuncAttributeMaxDynamicSharedMemorySize, GAT_SMEM);

    wh_kernel<<<BB * NN / 128, 256, 98304>>>(h, W, a);
    dim3 grid(NN / TI, BB);
    gat_kernel<<<grid, 256, GAT_SMEM>>>(adj, out);
}

// round 8
// speedup vs baseline: 2.9443x; 1.2686x over previous
#include <cuda_runtime.h>
#include <cuda_bf16.h>
#include <cuda_fp16.h>
#include <cstdint>
#include <math.h>

#define BB 8
#define NN 2048
#define FI 128
#define FO 64
#define KT 64
#define TI 64
#define NCHUNK (NN / KT)

// ---------------- scratch (static device arrays: allocation-free) ----------
__device__ __half g_Wh_h[(size_t)BB * NN * FO];  // [row][f] 2MB, fp16
__device__ float4 g_srow[BB * NN];   // (-s1, exp(s1), exp(0.2 s1), 0)
__device__ float4 g_scol[BB * NN];   // (s2, exp(s2), exp(0.2 s2), 0)

// ---------------- helpers ---------------------------------------------------
__device__ __forceinline__ uint32_t smem_u32(const void* p) {
    uint32_t a;
    asm("{ .reg .u64 t; cvta.to.shared.u64 t, %1; cvt.u32.u64 %0, t; }" : "=r"(a) : "l"(p));
    return a;
}

__device__ __forceinline__ void mma16816(float* c, uint32_t a0, uint32_t a1,
                                         uint32_t a2, uint32_t a3,
                                         uint32_t b0, uint32_t b1) {
    asm volatile("mma.sync.aligned.m16n8k16.row.col.f32.f16.f16.f32 "
                 "{%0,%1,%2,%3}, {%4,%5,%6,%7}, {%8,%9}, {%0,%1,%2,%3};"
                 : "+f"(c[0]), "+f"(c[1]), "+f"(c[2]), "+f"(c[3])
                 : "r"(a0), "r"(a1), "r"(a2), "r"(a3), "r"(b0), "r"(b1));
}

__device__ __forceinline__ void ldsm4t(uint32_t* r, uint32_t addr) {
    asm volatile("ldmatrix.sync.aligned.m8n8.x4.trans.shared.b16 {%0,%1,%2,%3}, [%4];"
                 : "=r"(r[0]), "=r"(r[1]), "=r"(r[2]), "=r"(r[3]) : "r"(addr));
}

__device__ __forceinline__ void cpasync16(uint32_t dst, const void* src) {
    asm volatile("cp.async.ca.shared.global [%0], [%1], 16;" :: "r"(dst), "l"(src));
}

__device__ __forceinline__ uint32_t packhf2(float x, float y) {
    __half2 v = __float22half2_rn(make_float2(x, y));
    return *(uint32_t*)&v;
}

__device__ __forceinline__ float f4c(const float4& v, int k) {
    return k == 0 ? v.x : (k == 1 ? v.y : (k == 2 ? v.z : v.w));
}

// p = adj ? (s1+s2>0 ? E1*E2 : F1*F2) : 0
// rp = (-s1, E1, F1, _)    sc = (s2, E2, F2, _)
__device__ __forceinline__ float pval(const float4& rp, const float4& sc, int adjv) {
    const bool gt = sc.x > rp.x;
    const float e1 = gt ? rp.y : rp.z;
    const float e2 = gt ? sc.y : sc.z;
    return adjv ? e1 * e2 : 0.f;
}

// ---------------------------------------------------------------------------
// Kernel 1: Wh = h @ W ; emits g_Wh_h ([row][f], fp16) + per-node attention
// tables g_srow / g_scol. 128 rows/block, thread tile 4 rows x 8 features.
// ---------------------------------------------------------------------------
__global__ void __launch_bounds__(256, 2) wh_kernel(const float* __restrict__ h,
                                                    const float* __restrict__ W,
                                                    const float* __restrict__ a) {
    extern __shared__ __align__(16) unsigned char smem_raw[];
    float4* sh4 = (float4*)smem_raw;                     // 128 x 128 f32 = 64KB
    float4* sW4 = (float4*)(smem_raw + 65536);           // 128 x 64 f32 = 32KB

    const int tid  = threadIdx.x;
    const int row0 = blockIdx.x * 128;

    const float4* hsrc = (const float4*)(h + (size_t)row0 * FI);
    #pragma unroll 4
    for (int i = tid; i < 128 * FI / 4; i += 256) sh4[i] = hsrc[i];
    const float4* wsrc = (const float4*)W;
    #pragma unroll 2
    for (int i = tid; i < FI * FO / 4; i += 256) sW4[i] = wsrc[i];
    __syncthreads();

    const int fg   = tid & 7;    // feature group: f0 = fg*8
    const int rowg = tid >> 3;   // 0..31: rows rowg*4 .. +3

    float acc[4][8];
    #pragma unroll
    for (int r = 0; r < 4; ++r)
        #pragma unroll
        for (int c = 0; c < 8; ++c) acc[r][c] = 0.f;

    #pragma unroll 2
    for (int k4 = 0; k4 < FI / 4; ++k4) {
        float4 hv[4];
        #pragma unroll
        for (int r = 0; r < 4; ++r) hv[r] = sh4[(rowg * 4 + r) * (FI / 4) + k4];
        #pragma unroll
        for (int kk = 0; kk < 4; ++kk) {
            const float4 wa = sW4[(k4 * 4 + kk) * 16 + fg * 2];
            const float4 wb = sW4[(k4 * 4 + kk) * 16 + fg * 2 + 1];
            #pragma unroll
            for (int r = 0; r < 4; ++r) {
                const float hk = f4c(hv[r], kk);
                acc[r][0] = fmaf(hk, wa.x, acc[r][0]);
                acc[r][1] = fmaf(hk, wa.y, acc[r][1]);
                acc[r][2] = fmaf(hk, wa.z, acc[r][2]);
                acc[r][3] = fmaf(hk, wa.w, acc[r][3]);
                acc[r][4] = fmaf(hk, wb.x, acc[r][4]);
                acc[r][5] = fmaf(hk, wb.y, acc[r][5]);
                acc[r][6] = fmaf(hk, wb.z, acc[r][6]);
                acc[r][7] = fmaf(hk, wb.w, acc[r][7]);
            }
        }
    }

    // ---- s1/s2 partials over this thread's 8 features, reduce over fg lanes
    const float4* a4 = (const float4*)a;
    const float4 a1a = a4[fg * 2], a1b = a4[fg * 2 + 1];
    const float4 a2a = a4[16 + fg * 2], a2b = a4[16 + fg * 2 + 1];
    float s1p[4], s2p[4];
    #pragma unroll
    for (int r = 0; r < 4; ++r) {
        s1p[r] = acc[r][0] * a1a.x + acc[r][1] * a1a.y + acc[r][2] * a1a.z + acc[r][3] * a1a.w
               + acc[r][4] * a1b.x + acc[r][5] * a1b.y + acc[r][6] * a1b.z + acc[r][7] * a1b.w;
        s2p[r] = acc[r][0] * a2a.x + acc[r][1] * a2a.y + acc[r][2] * a2a.z + acc[r][3] * a2a.w
               + acc[r][4] * a2b.x + acc[r][5] * a2b.y + acc[r][6] * a2b.z + acc[r][7] * a2b.w;
    }
    #pragma unroll
    for (int off = 1; off < 8; off <<= 1)
        #pragma unroll
        for (int r = 0; r < 4; ++r) {
            s1p[r] += __shfl_xor_sync(0xffffffffu, s1p[r], off);
            s2p[r] += __shfl_xor_sync(0xffffffffu, s2p[r], off);
        }
    if (fg == 0) {
        #pragma unroll
        for (int r = 0; r < 4; ++r) {
            const int row = row0 + rowg * 4 + r;
            const float s1 = s1p[r], s2 = s2p[r];
            g_srow[row] = make_float4(-s1, __expf(s1), __expf(0.2f * s1), 0.f);
            g_scol[row] = make_float4(s2, __expf(s2), __expf(0.2f * s2), 0.f);
        }
    }

    // ---- fp16 plane, natural [row][f] layout
    #pragma unroll
    for (int r = 0; r < 4; ++r) {
        const int row = row0 + rowg * 4 + r;
        uint32_t hw[4];
        #pragma unroll
        for (int cp = 0; cp < 4; ++cp)
            hw[cp] = packhf2(acc[r][cp * 2], acc[r][cp * 2 + 1]);
        *(uint4*)(g_Wh_h + (size_t)row * FO + fg * 8) = make_uint4(hw[0], hw[1], hw[2], hw[3]);
    }
}

// ---------------------------------------------------------------------------
// Kernel 2: fused GAT attention via mma.sync fp16 (single plane), K-split.
// CTA: 64 i-rows x 64 f. Warp pair (p, p+4): rows p*16..+15; warp p handles
// k-slices 0-1 (j 0-31 of chunk), warp p+4 k-slices 2-3 (j 32-63); each
// covers all 64 output cols. fp32 partial accs merged in the epilogue.
// ---------------------------------------------------------------------------
#define SB_STRIDE 144            // 64 fp16 + 16B pad
#define SB_PLANE  (64 * SB_STRIDE)
#define OFF_SB    32768
#define ACC_STRIDE 68            // padded f32 stride for acc exchange
#define OFF_SROW  (OFF_SB + 18432)          // 51200 (2*64 floats)
#define GAT_SMEM  (OFF_SROW + 512)          // 51712

__device__ __forceinline__ void stage_chunk(uint32_t sb, int buf, int rowbase, int tid) {
    #pragma unroll
    for (int q = 0; q < 2; ++q) {
        const int id  = tid + q * 256;     // 0..511
        const int row = id >> 3;
        const int c16 = id & 7;
        const __half* src = g_Wh_h + (size_t)(rowbase + row) * FO + c16 * 8;
        const uint32_t dst = sb + buf * SB_PLANE + row * SB_STRIDE + c16 * 16;
        cpasync16(dst, src);
    }
}

__global__ void __launch_bounds__(256, 2) gat_kernel(const int* __restrict__ adj,
                                                     float* __restrict__ out) {
    extern __shared__ __align__(16) unsigned char smem_raw[];
    float4* scol = (float4*)smem_raw;                       // 32KB
    float*  srow = (float*)(smem_raw + OFF_SROW);           // [2][64]
    float*  accbuf = (float*)(smem_raw + OFF_SB);           // 64 x ACC_STRIDE f32
    const uint32_t sb = smem_u32(smem_raw) + OFF_SB;

    const int tid  = threadIdx.x;
    const int lane = tid & 31;
    const int wid  = tid >> 5;
    const int b    = blockIdx.y;
    const int i0   = blockIdx.x * TI;

    const int mb    = (wid & 3) * 16;   // warp row base (local, 0..48)
    const int khalf = wid >> 2;         // 0: k-slices 0-1, 1: k-slices 2-3
    const int lrl = mb + (lane >> 2);   // local row (lo)
    const int lrh = lrl + 8;
    const int qc  = (lane & 3) * 2;     // k-pair base within 16

    // preload scol for batch b (f32 tables: exact P)
    {
        const float4* src = (const float4*)(g_scol + b * NN);
        #pragma unroll 2
        for (int i = tid; i < NN; i += 256) scol[i] = src[i];
    }

    const float4 rp_lo = g_srow[b * NN + i0 + lrl];
    const float4 rp_hi = g_srow[b * NN + i0 + lrh];
    const int* adjl = adj + (size_t)(b * NN + i0 + lrl) * NN;
    const int* adjh = adj + (size_t)(b * NN + i0 + lrh) * NN;

    stage_chunk(sb, 0, b * NN, tid);
    asm volatile("cp.async.commit_group;" ::: "memory");
    __syncthreads();   // scol visible

    float acc[8][4];
    #pragma unroll
    for (int nt = 0; nt < 8; ++nt)
        #pragma unroll
        for (int k = 0; k < 4; ++k) acc[nt][k] = 0.f;
    float rsum_lo = 0.f, rsum_hi = 0.f;

    const int lrow = (lane & 7) + (lane & 8);       // ldmatrix row 0..15
    const int lcol = (lane >> 4) << 3;              // 0 or 8

    #pragma unroll 1
    for (int t = 0; t < NCHUNK; ++t) {
        if (t + 1 < NCHUNK) {
            stage_chunk(sb, (t + 1) & 1, b * NN + (t + 1) * KT, tid);
            asm volatile("cp.async.commit_group;" ::: "memory");
            asm volatile("cp.async.wait_group 1;" ::: "memory");
        } else {
            asm volatile("cp.async.wait_group 0;" ::: "memory");
        }
        __syncthreads();   // chunk t landed everywhere

        const uint32_t bufh = sb + (t & 1) * SB_PLANE;
        const int j0 = t * KT;

        #pragma unroll
        for (int kt2 = 0; kt2 < 2; ++kt2) {
            const int ktg = khalf * 2 + kt2;          // this warp's k-slice
            const int c0  = j0 + ktg * 16 + qc;
            const float4 sc0 = scol[c0];
            const float4 sc1 = scol[c0 + 1];
            const float4 sc8 = scol[c0 + 8];
            const float4 sc9 = scol[c0 + 9];
            const int2 al0 = *(const int2*)(adjl + c0);
            const int2 al8 = *(const int2*)(adjl + c0 + 8);
            const int2 ah0 = *(const int2*)(adjh + c0);
            const int2 ah8 = *(const int2*)(adjh + c0 + 8);

            const float pl0 = pval(rp_lo, sc0, al0.x);
            const float pl1 = pval(rp_lo, sc1, al0.y);
            const float pl8 = pval(rp_lo, sc8, al8.x);
            const float pl9 = pval(rp_lo, sc9, al8.y);
            const float ph0 = pval(rp_hi, sc0, ah0.x);
            const float ph1 = pval(rp_hi, sc1, ah0.y);
            const float ph8 = pval(rp_hi, sc8, ah8.x);
            const float ph9 = pval(rp_hi, sc9, ah8.y);

            rsum_lo += (pl0 + pl1) + (pl8 + pl9);
            rsum_hi += (ph0 + ph1) + (ph8 + ph9);

            const uint32_t a0 = packhf2(pl0, pl1);
            const uint32_t a1 = packhf2(ph0, ph1);
            const uint32_t a2 = packhf2(pl8, pl9);
            const uint32_t a3 = packhf2(ph8, ph9);

            // all 64 cols, 16 at a time (keeps B-reg pressure at 4)
            const uint32_t rowoff = (uint32_t)(ktg * 16 + lrow) * SB_STRIDE + lcol * 2;
            #pragma unroll
            for (int ci = 0; ci < 4; ++ci) {
                uint32_t bt[4];
                ldsm4t(bt, bufh + rowoff + ci * 32);
                mma16816(acc[ci * 2 + 0], a0, a1, a2, a3, bt[0], bt[1]);
                mma16816(acc[ci * 2 + 1], a0, a1, a2, a3, bt[2], bt[3]);
            }
        }
        __syncthreads();   // all reads of buf t done before it is re-staged
    }

    // ---- rowsum partials (per khalf) -> smem
    rsum_lo += __shfl_xor_sync(0xffffffffu, rsum_lo, 1);
    rsum_lo += __shfl_xor_sync(0xffffffffu, rsum_lo, 2);
    rsum_hi += __shfl_xor_sync(0xffffffffu, rsum_hi, 1);
    rsum_hi += __shfl_xor_sync(0xffffffffu, rsum_hi, 2);
    if ((lane & 3) == 0) {
        srow[khalf * 64 + lrl] = rsum_lo;
        srow[khalf * 64 + lrh] = rsum_hi;
    }

    // ---- acc merge: khalf=1 publishes partials (staging area reusable now)
    if (khalf) {
        #pragma unroll
        for (int nt = 0; nt < 8; ++nt) {
            *(float2*)(accbuf + lrl * ACC_STRIDE + nt * 8 + qc) =
                make_float2(acc[nt][0], acc[nt][1]);
            *(float2*)(accbuf + lrh * ACC_STRIDE + nt * 8 + qc) =
                make_float2(acc[nt][2], acc[nt][3]);
        }
    }
    __syncthreads();

    if (!khalf) {
        const float invl = 1.0f / (srow[lrl] + srow[64 + lrl]);
        const float invh = 1.0f / (srow[lrh] + srow[64 + lrh]);
        float* outl = out + (size_t)(b * NN + i0 + lrl) * FO;
        float* outh = out + (size_t)(b * NN + i0 + lrh) * FO;
        #pragma unroll
        for (int nt = 0; nt < 8; ++nt) {
            const int cb = nt * 8 + qc;
            const float2 tl = *(const float2*)(accbuf + lrl * ACC_STRIDE + cb);
            const float2 th = *(const float2*)(accbuf + lrh * ACC_STRIDE + cb);
            float2 o;
            float v;
            v = (acc[nt][0] + tl.x) * invl; o.x = (v > 0.f) ? v : expm1f(v);
            v = (acc[nt][1] + tl.y) * invl; o.y = (v > 0.f) ? v : expm1f(v);
            *(float2*)(outl + cb) = o;
            v = (acc[nt][2] + th.x) * invh; o.x = (v > 0.f) ? v : expm1f(v);
            v = (acc[nt][3] + th.y) * invh; o.y = (v > 0.f) ? v : expm1f(v);
            *(float2*)(outh + cb) = o;
        }
    }
}

// ---------------------------------------------------------------------------
extern "C" void kernel_launch(void* const* d_in, const int* in_sizes, int n_in,
                              void* d_out, int out_size) {
    const float* h   = (const float*)d_in[0];   // [8,2048,128] f32
    const float* W   = (const float*)d_in[1];   // [128,64] f32
    const float* a   = (const float*)d_in[2];   // [128,1] f32
    const int*   adj = (const int*)d_in[3];     // [8,2048,2048] i32
    float* out = (float*)d_out;                 // [8,2048,64] f32

    cudaFuncSetAttribute(wh_kernel, cudaFuncAttributeMaxDynamicSharedMemorySize, 98304);
    cudaFuncSetAttribute(gat_kernel, cudaFuncAttributeMaxDynamicSharedMemorySize, GAT_SMEM);

    wh_kernel<<<BB * NN / 128, 256, 98304>>>(h, W, a);
    dim3 grid(NN / TI, BB);
    gat_kernel<<<grid, 256, GAT_SMEM>>>(adj, out);
}